// round 1
// baseline (speedup 1.0000x reference)
#include <cuda_runtime.h>

// Resampling_79353815760907
// input_fmap: (B=16, P=4, H=32, W=32, D=32, C=8) float32
// theta:      (B=16, P=4, 3, 4) float32
// out:        (B, P, H, W, D, C) float32
//
// Reference semantics (kept faithfully, including quirks):
//   xt = w-index, yt = h-index, zt = d-index  (meshgrid 'xy')
//   x = t00*w + t01*h + t02*d + t03 + 2   (and y,z rows 1,2)
//   x0 = clip(floor(x), 0, 34) ; x1 = x0+1 (NOT re-clipped)
//   gather padded[b,p, xi, yi, zi, :]  -- xi indexes the H axis (cross-wired)
//   padded = pad 2 zeros each side of H,W,D -> orig index = xi-2, zero if OOB
//   xd = x - x0 (post-clip), trilinear blend.

#define BB 16
#define PP 4
#define HH 32
#define WW 32
#define DD 32
#define CC 8

__global__ void __launch_bounds__(256, 8)
resample_kernel(const float* __restrict__ fmap,
                const float* __restrict__ theta,
                float* __restrict__ out) {
    const int idx = blockIdx.x * blockDim.x + threadIdx.x;  // over B*P*H*W*D
    // dims are all 32 -> shift/mask decompose; innermost = d
    const int d  = idx & 31;
    const int w  = (idx >> 5) & 31;
    const int h  = (idx >> 10) & 31;
    const int bp = idx >> 15;               // b*P + p  in [0, 64)

    // theta for this (b,p): 12 floats. Whole block shares one bp -> uniform,
    // L1-resident after first touch.
    const float* __restrict__ th = theta + bp * 12;
    const float fw = (float)w, fh = (float)h, fd = (float)d;

    const float x = fmaf(th[0], fw, fmaf(th[1], fh, fmaf(th[2],  fd, th[3])))  + 2.0f;
    const float y = fmaf(th[4], fw, fmaf(th[5], fh, fmaf(th[6],  fd, th[7])))  + 2.0f;
    const float z = fmaf(th[8], fw, fmaf(th[9], fh, fmaf(th[10], fd, th[11]))) + 2.0f;

    // clip(floor, 0, H+2=34)
    int x0 = min(max((int)floorf(x), 0), 34);
    int y0 = min(max((int)floorf(y), 0), 34);
    int z0 = min(max((int)floorf(z), 0), 34);

    const float xd = x - (float)x0;
    const float yd = y - (float)y0;
    const float zd = z - (float)z0;

    const float wx1 = xd, wx0 = 1.0f - xd;
    const float wy1 = yd, wy0 = 1.0f - yd;
    const float wz1 = zd, wz0 = 1.0f - zd;

    // convert padded indices -> original indices (pad = 2)
    const int ox0 = x0 - 2, ox1 = ox0 + 1;
    const int oy0 = y0 - 2, oy1 = oy0 + 1;
    const int oz0 = z0 - 2, oz1 = oz0 + 1;

    const bool vx0 = (unsigned)ox0 < 32u, vx1 = (unsigned)ox1 < 32u;
    const bool vy0 = (unsigned)oy0 < 32u, vy1 = (unsigned)oy1 < 32u;
    const bool vz0 = (unsigned)oz0 < 32u, vz1 = (unsigned)oz1 < 32u;

    const float* __restrict__ base = fmap + (size_t)bp * (HH * WW * DD * CC);

    float4 lo = make_float4(0.f, 0.f, 0.f, 0.f);
    float4 hi = make_float4(0.f, 0.f, 0.f, 0.f);

    // corner accumulate macro: xi indexes H axis, yi indexes W axis, zi indexes D axis
    #define CORNER(vx, vy, vz, xi, yi, zi, wgt)                                        \
        if ((vx) && (vy) && (vz)) {                                                    \
            const float4* __restrict__ p =                                             \
                (const float4*)(base + ((((xi) * 32 + (yi)) * 32 + (zi)) << 3));       \
            const float4 a = __ldg(p);                                                 \
            const float4 b = __ldg(p + 1);                                             \
            const float ww_ = (wgt);                                                   \
            lo.x = fmaf(ww_, a.x, lo.x); lo.y = fmaf(ww_, a.y, lo.y);                  \
            lo.z = fmaf(ww_, a.z, lo.z); lo.w = fmaf(ww_, a.w, lo.w);                  \
            hi.x = fmaf(ww_, b.x, hi.x); hi.y = fmaf(ww_, b.y, hi.y);                  \
            hi.z = fmaf(ww_, b.z, hi.z); hi.w = fmaf(ww_, b.w, hi.w);                  \
        }

    CORNER(vx0, vy0, vz0, ox0, oy0, oz0, wx0 * wy0 * wz0)
    CORNER(vx0, vy0, vz1, ox0, oy0, oz1, wx0 * wy0 * wz1)
    CORNER(vx0, vy1, vz0, ox0, oy1, oz0, wx0 * wy1 * wz0)
    CORNER(vx0, vy1, vz1, ox0, oy1, oz1, wx0 * wy1 * wz1)
    CORNER(vx1, vy0, vz0, ox1, oy0, oz0, wx1 * wy0 * wz0)
    CORNER(vx1, vy0, vz1, ox1, oy0, oz1, wx1 * wy0 * wz1)
    CORNER(vx1, vy1, vz0, ox1, oy1, oz0, wx1 * wy1 * wz0)
    CORNER(vx1, vy1, vz1, ox1, oy1, oz1, wx1 * wy1 * wz1)
    #undef CORNER

    float4* __restrict__ o = (float4*)(out + ((size_t)idx << 3));
    o[0] = lo;
    o[1] = hi;
}

extern "C" void kernel_launch(void* const* d_in, const int* in_sizes, int n_in,
                              void* d_out, int out_size) {
    const float* fmap  = (const float*)d_in[0];
    const float* theta = (const float*)d_in[1];
    float* out = (float*)d_out;

    const int total = BB * PP * HH * WW * DD;  // 2,097,152 spatial points
    const int threads = 256;
    const int blocks = total / threads;        // 8192
    resample_kernel<<<blocks, threads>>>(fmap, theta, out);
}

// round 2
// speedup vs baseline: 1.3259x; 1.3259x over previous
#include <cuda_runtime.h>

// Resampling_79353815760907
// input_fmap: (B=16, P=4, H=32, W=32, D=32, C=8) float32
// theta:      (B=16, P=4, 3, 4) float32
// out:        (B, P, H, W, D, C) float32
//
// Round 2: 2 threads per spatial point (each handles 4 of the 8 channels).
// Each corner gather is a single LDG.128 whose warp-address pattern strides
// 16 B contiguously -> fully-packed L1 wavefronts (vs 50%-efficient before).
//
// Reference semantics (kept faithfully, including quirks):
//   x = t00*w + t01*h + t02*d + t03 + 2  (rows 1,2 for y,z)
//   x0 = clip(floor(x), 0, 34); x1 = x0+1 (NOT re-clipped)
//   gather padded[b,p, xi, yi, zi, :]  -- xi indexes the H axis (cross-wired)
//   padded = pad 2 each side -> orig index = xi-2, zero outside [0,32)
//   xd = x - x0 (post-clip), trilinear blend.

#define BB 16
#define PP 4
#define HH 32
#define WW 32
#define DD 32
#define CC 8

__global__ void __launch_bounds__(256, 8)
resample_kernel(const float* __restrict__ fmap,
                const float* __restrict__ theta,
                float* __restrict__ out) {
    const int g    = blockIdx.x * blockDim.x + threadIdx.x;  // 2 threads / point
    const int half = g & 1;         // 0 -> channels 0..3, 1 -> channels 4..7
    const int idx  = g >> 1;        // spatial point over B*P*H*W*D

    const int d  = idx & 31;
    const int w  = (idx >> 5) & 31;
    const int h  = (idx >> 10) & 31;
    const int bp = idx >> 15;       // b*P + p in [0, 64)

    const float* __restrict__ th = theta + bp * 12;
    const float fw = (float)w, fh = (float)h, fd = (float)d;

    const float x = fmaf(th[0], fw, fmaf(th[1], fh, fmaf(th[2],  fd, th[3])))  + 2.0f;
    const float y = fmaf(th[4], fw, fmaf(th[5], fh, fmaf(th[6],  fd, th[7])))  + 2.0f;
    const float z = fmaf(th[8], fw, fmaf(th[9], fh, fmaf(th[10], fd, th[11]))) + 2.0f;

    // clip(floor, 0, H+2=34)
    const int x0 = min(max((int)floorf(x), 0), 34);
    const int y0 = min(max((int)floorf(y), 0), 34);
    const int z0 = min(max((int)floorf(z), 0), 34);

    const float xd = x - (float)x0;
    const float yd = y - (float)y0;
    const float zd = z - (float)z0;

    const float wx1 = xd, wx0 = 1.0f - xd;
    const float wy1 = yd, wy0 = 1.0f - yd;
    const float wz1 = zd, wz0 = 1.0f - zd;

    // padded -> original indices (pad = 2)
    const int ox0 = x0 - 2, ox1 = ox0 + 1;
    const int oy0 = y0 - 2, oy1 = oy0 + 1;
    const int oz0 = z0 - 2, oz1 = oz0 + 1;

    const bool vx0 = (unsigned)ox0 < 32u, vx1 = (unsigned)ox1 < 32u;
    const bool vy0 = (unsigned)oy0 < 32u, vy1 = (unsigned)oy1 < 32u;
    const bool vz0 = (unsigned)oz0 < 32u, vz1 = (unsigned)oz1 < 32u;

    // base for this (b,p) plus this thread's 16-byte half of the channel vector
    const float* __restrict__ base =
        fmap + (size_t)bp * (HH * WW * DD * CC) + (half << 2);

    float4 acc = make_float4(0.f, 0.f, 0.f, 0.f);

    // xi indexes H axis, yi indexes W axis, zi indexes D axis (reference quirk)
    #define CORNER(vx, vy, vz, xi, yi, zi, wgt)                                  \
        if ((vx) && (vy) && (vz)) {                                              \
            const float4 a = __ldg((const float4*)(                              \
                base + ((((xi) * 32 + (yi)) * 32 + (zi)) << 3)));                \
            const float ww_ = (wgt);                                             \
            acc.x = fmaf(ww_, a.x, acc.x);                                       \
            acc.y = fmaf(ww_, a.y, acc.y);                                       \
            acc.z = fmaf(ww_, a.z, acc.z);                                       \
            acc.w = fmaf(ww_, a.w, acc.w);                                       \
        }

    CORNER(vx0, vy0, vz0, ox0, oy0, oz0, wx0 * wy0 * wz0)
    CORNER(vx0, vy0, vz1, ox0, oy0, oz1, wx0 * wy0 * wz1)
    CORNER(vx0, vy1, vz0, ox0, oy1, oz0, wx0 * wy1 * wz0)
    CORNER(vx0, vy1, vz1, ox0, oy1, oz1, wx0 * wy1 * wz1)
    CORNER(vx1, vy0, vz0, ox1, oy0, oz0, wx1 * wy0 * wz0)
    CORNER(vx1, vy0, vz1, ox1, oy0, oz1, wx1 * wy0 * wz1)
    CORNER(vx1, vy1, vz0, ox1, oy1, oz0, wx1 * wy1 * wz0)
    CORNER(vx1, vy1, vz1, ox1, oy1, oz1, wx1 * wy1 * wz1)
    #undef CORNER

    float4* __restrict__ o = (float4*)(out + ((size_t)idx << 3) + (half << 2));
    *o = acc;
}

extern "C" void kernel_launch(void* const* d_in, const int* in_sizes, int n_in,
                              void* d_out, int out_size) {
    const float* fmap  = (const float*)d_in[0];
    const float* theta = (const float*)d_in[1];
    float* out = (float*)d_out;

    const int total_threads = BB * PP * HH * WW * DD * 2;  // 2 threads / point
    const int threads = 256;
    const int blocks = total_threads / threads;            // 16384
    resample_kernel<<<blocks, threads>>>(fmap, theta, out);
}